// round 1
// baseline (speedup 1.0000x reference)
#include <cuda_runtime.h>

// Problem constants
#define B_  8
#define C_  64
#define H_  128
#define W_  128
#define OC_ 128
#define HP_ 130           // padded H
#define WP_ 130           // padded W
#define RS_ 132           // padded row stride (floats)
#define PS_ (RS_ * HP_)   // plane stride = 17160

// Scratch: E = exp(x) with a ring of 1.0f (exp(0)) around each plane,
// Cs = per-pixel channel sum of E (border pixels = 64.0).
__device__ float g_E[(size_t)B_ * C_ * PS_];   // ~35 MB
__device__ float g_Cs[(size_t)B_ * PS_];       // ~0.55 MB

// ---------------------------------------------------------------------------
// Kernel A: E = exp(x) (interior), 1.0 (border ring); Cs = sum_c E
// ---------------------------------------------------------------------------
__global__ void exp_kernel(const float* __restrict__ x) {
    int idx = blockIdx.x * blockDim.x + threadIdx.x;
    const int total = B_ * HP_ * WP_;
    if (idx >= total) return;
    int b  = idx / (HP_ * WP_);
    int r  = idx - b * (HP_ * WP_);
    int hp = r / WP_;
    int wp = r - hp * WP_;

    float* Eb = g_E + (size_t)b * C_ * PS_ + hp * RS_ + wp;
    if (hp == 0 || hp == HP_ - 1 || wp == 0 || wp == WP_ - 1) {
        #pragma unroll 8
        for (int c = 0; c < C_; c++) Eb[c * PS_] = 1.0f;
        g_Cs[(size_t)b * PS_ + hp * RS_ + wp] = 64.0f;
    } else {
        const float* xb = x + (size_t)b * C_ * H_ * W_ + (hp - 1) * W_ + (wp - 1);
        float s = 0.0f;
        #pragma unroll 8
        for (int c = 0; c < C_; c++) {
            float v = __expf(xb[c * H_ * W_]);
            Eb[c * PS_] = v;
            s += v;
        }
        g_Cs[(size_t)b * PS_ + hp * RS_ + wp] = s;
    }
}

// ---------------------------------------------------------------------------
// Kernel B: 3x3 conv (64 -> 128 ch) over g_E, divided by 3x3 boxsum of g_Cs.
// Block: 128 oc x (4 rows x 32 cols) pixels. 256 threads.
// Thread: 8 oc x 8 pixels (one row, 8 consecutive cols) = 64 accumulators.
// ---------------------------------------------------------------------------
#define CC_ 8     // input-channel chunk
#define ER_ 6     // E tile rows (4 + 2 halo)
#define EWU_ 34   // E tile cols used (32 + 2 halo)
#define EW_ 40    // E tile col stride (padded)

__global__ __launch_bounds__(256) void conv_kernel(const float* __restrict__ mem,
                                                   float* __restrict__ out) {
    __shared__ float Wsm[CC_ * 9 * OC_];       // 9216 floats = 36 KB
    __shared__ float Esm[CC_][ER_][EW_];       // 1920 floats = 7.5 KB

    const int b  = blockIdx.z;
    const int h0 = blockIdx.y * 4;
    const int w0 = blockIdx.x * 32;
    const int tid   = threadIdx.x;
    const int oc_t  = tid & 15;          // 0..15 -> oc base = oc_t*8
    const int pix_t = tid >> 4;          // 0..15
    const int pr = pix_t >> 2;           // row in tile 0..3
    const int pc = (pix_t & 3) * 8;      // col base in tile 0,8,16,24

    float acc[8][8];
    #pragma unroll
    for (int i = 0; i < 8; i++)
        #pragma unroll
        for (int j = 0; j < 8; j++) acc[i][j] = 0.0f;

    const float* Ebase = g_E + (size_t)b * C_ * PS_;

    for (int c0 = 0; c0 < C_; c0 += CC_) {
        __syncthreads();
        // Weights for this channel chunk: k index = c*9 + kh*3 + kw, row len 128
        // -> a contiguous slab of `memory`. Straight copy.
        {
            const float* msrc = mem + c0 * 9 * OC_;
            #pragma unroll 4
            for (int i = tid; i < CC_ * 9 * OC_; i += 256) Wsm[i] = msrc[i];
        }
        // E tile: rows h0..h0+5, cols w0..w0+33 (padded coords)
        for (int i = tid; i < CC_ * ER_ * EWU_; i += 256) {
            int cc = i / (ER_ * EWU_);
            int rr = (i / EWU_) % ER_;
            int jj = i % EWU_;
            Esm[cc][rr][jj] = Ebase[(size_t)(c0 + cc) * PS_ + (h0 + rr) * RS_ + (w0 + jj)];
        }
        __syncthreads();

        #pragma unroll
        for (int cc = 0; cc < CC_; cc++) {
            #pragma unroll
            for (int kh = 0; kh < 3; kh++) {
                float e[10];
                #pragma unroll
                for (int j = 0; j < 10; j++) e[j] = Esm[cc][pr + kh][pc + j];
                #pragma unroll
                for (int kw = 0; kw < 3; kw++) {
                    const float4* wp4 =
                        (const float4*)&Wsm[(cc * 9 + kh * 3 + kw) * OC_ + oc_t * 8];
                    float4 wa = wp4[0], wb = wp4[1];
                    float wv[8] = {wa.x, wa.y, wa.z, wa.w, wb.x, wb.y, wb.z, wb.w};
                    #pragma unroll
                    for (int i = 0; i < 8; i++)
                        #pragma unroll
                        for (int j = 0; j < 8; j++)
                            acc[i][j] = fmaf(wv[i], e[kw + j], acc[i][j]);
                }
            }
        }
    }

    // Normalizer Z = 3x3 boxsum of channel sums (padded coords h..h+2, w..w+2)
    const int h = h0 + pr;
    const int w = w0 + pc;
    const float* Cb = g_Cs + (size_t)b * PS_;
    float rz[8];
    {
        float rowsum[10];
        #pragma unroll
        for (int j = 0; j < 10; j++)
            rowsum[j] = Cb[(h + 0) * RS_ + w + j]
                      + Cb[(h + 1) * RS_ + w + j]
                      + Cb[(h + 2) * RS_ + w + j];
        #pragma unroll
        for (int j = 0; j < 8; j++)
            rz[j] = __frcp_rn(rowsum[j] + rowsum[j + 1] + rowsum[j + 2]);
    }

    // Write out[b][oc][h][w], 8 oc x 8 consecutive cols, float4-aligned
    float* ob = out + ((size_t)b * OC_ + oc_t * 8) * H_ * W_ + h * W_ + w;
    #pragma unroll
    for (int i = 0; i < 8; i++) {
        float4 v0 = make_float4(acc[i][0] * rz[0], acc[i][1] * rz[1],
                                acc[i][2] * rz[2], acc[i][3] * rz[3]);
        float4 v1 = make_float4(acc[i][4] * rz[4], acc[i][5] * rz[5],
                                acc[i][6] * rz[6], acc[i][7] * rz[7]);
        *(float4*)(ob + (size_t)i * H_ * W_)     = v0;
        *(float4*)(ob + (size_t)i * H_ * W_ + 4) = v1;
    }
}

// ---------------------------------------------------------------------------
extern "C" void kernel_launch(void* const* d_in, const int* in_sizes, int n_in,
                              void* d_out, int out_size) {
    const float* x   = (const float*)d_in[0];  // [8,64,128,128]
    const float* mem = (const float*)d_in[1];  // [576,128]
    float* out = (float*)d_out;                // [8,128,128,128]

    const int total = B_ * HP_ * WP_;
    exp_kernel<<<(total + 127) / 128, 128>>>(x);

    dim3 grid(W_ / 32, H_ / 4, B_);            // (4, 32, 8) = 1024 blocks
    conv_kernel<<<grid, 256>>>(mem, out);
}

// round 3
// speedup vs baseline: 7.0189x; 7.0189x over previous
#include <cuda_runtime.h>
#include <cuda_bf16.h>
#include <cstdint>

#define B_  8
#define C_  64
#define H_  128
#define W_  128
#define OC_ 128
#define HP_ 130
#define WP_ 130

// E transposed: [b][hp][wp][c] bf16, border ring = 1.0 (= exp(0))
__device__ __nv_bfloat16 g_Egt[(size_t)B_ * HP_ * WP_ * C_];  // ~17.3 MB
__device__ float         g_Cs[(size_t)B_ * HP_ * WP_];        // channel sums, ring = 64
__device__ __nv_bfloat16 g_Wr[9 * OC_ * C_];                  // [tap][oc][c]

// ---------------------------------------------------------------------------
// Helpers (all plain sm_80-era PTX — no arch-accelerated features)
// ---------------------------------------------------------------------------
__device__ __forceinline__ uint32_t smem_u32(const void* p) {
    uint32_t a;
    asm("{ .reg .u64 t; cvta.to.shared.u64 t, %1; cvt.u32.u64 %0, t; }" : "=r"(a) : "l"(p));
    return a;
}
#define CP_ASYNC16(sa, ga) \
    asm volatile("cp.async.cg.shared.global [%0], [%1], 16;" :: "r"(sa), "l"(ga) : "memory")
#define CP_COMMIT() asm volatile("cp.async.commit_group;" ::: "memory")
#define CP_WAIT(n)  asm volatile("cp.async.wait_group %0;" :: "n"(n) : "memory")
#define LDSM_X4(r0, r1, r2, r3, addr) \
    asm volatile("ldmatrix.sync.aligned.m8n8.x4.shared.b16 {%0,%1,%2,%3}, [%4];" \
        : "=r"(r0), "=r"(r1), "=r"(r2), "=r"(r3) : "r"(addr))

__device__ __forceinline__ void mma16816(float* c, const uint32_t* a,
                                         uint32_t b0, uint32_t b1) {
    asm volatile(
        "mma.sync.aligned.m16n8k16.row.col.f32.bf16.bf16.f32 "
        "{%0,%1,%2,%3}, {%4,%5,%6,%7}, {%8,%9}, {%0,%1,%2,%3};"
        : "+f"(c[0]), "+f"(c[1]), "+f"(c[2]), "+f"(c[3])
        : "r"(a[0]), "r"(a[1]), "r"(a[2]), "r"(a[3]), "r"(b0), "r"(b1));
}

// ---------------------------------------------------------------------------
// Weights -> Wr[tap][oc][c] bf16   (memory index k = c*9 + kh*3 + kw)
// ---------------------------------------------------------------------------
__global__ void prep_w_kernel(const float* __restrict__ mem) {
    int idx = blockIdx.x * 256 + threadIdx.x;
    if (idx >= 9 * OC_ * C_) return;
    int c   = idx & 63;
    int oc  = (idx >> 6) & 127;
    int tap = idx >> 13;
    g_Wr[idx] = __float2bfloat16(mem[(c * 9 + tap) * OC_ + oc]);
}

// ---------------------------------------------------------------------------
// Border ring of Egt = 1.0 (exp(0)), Cs ring = 64
// ---------------------------------------------------------------------------
__global__ void border_kernel() {
    int idx = blockIdx.x * 128 + threadIdx.x;
    if (idx >= B_ * 516) return;
    int b = idx / 516, p = idx % 516;
    int hp, wp;
    if (p < 260) { hp = (p < 130) ? 0 : (HP_ - 1); wp = p % 130; }
    else { int q = p - 260; hp = 1 + (q & 127); wp = (q < 128) ? 0 : (WP_ - 1); }
    size_t pix = ((size_t)b * HP_ + hp) * WP_ + wp;
    uint4 ones = make_uint4(0x3F803F80u, 0x3F803F80u, 0x3F803F80u, 0x3F803F80u);
    uint4* dst = reinterpret_cast<uint4*>(g_Egt + pix * C_);
#pragma unroll
    for (int i = 0; i < 8; i++) dst[i] = ones;
    g_Cs[pix] = 64.0f;
}

// ---------------------------------------------------------------------------
// E = exp(x), transpose to channel-contiguous bf16, channel sums
// Tile: one h row, 64 pixels x 64 channels. Grid (2, 128, 8), 256 thr.
// ---------------------------------------------------------------------------
__global__ __launch_bounds__(256) void exp_kernel(const float* __restrict__ x) {
    __shared__ float sm[C_][65];
    const int b = blockIdx.z, h = blockIdx.y, w0 = blockIdx.x * 64;
    const int tid = threadIdx.x;
    const int px = tid & 63, cq = tid >> 6;

    const float* xb = x + (((size_t)b * C_) * H_ + h) * W_ + w0 + px;
#pragma unroll
    for (int it = 0; it < 16; it++) {
        int c = it * 4 + cq;
        sm[c][px] = __expf(xb[(size_t)c * H_ * W_]);
    }
    __syncthreads();

    if (tid < 64) {
        float s = 0.f;
#pragma unroll
        for (int c = 0; c < C_; c++) s += sm[c][tid];
        g_Cs[((size_t)b * HP_ + h + 1) * WP_ + (w0 + tid + 1)] = s;
    }

    const int seg = tid & 7, r0 = tid >> 3;
#pragma unroll
    for (int pass = 0; pass < 2; pass++) {
        int r = pass * 32 + r0;
        uint32_t pk[4];
#pragma unroll
        for (int j = 0; j < 4; j++) {
            __nv_bfloat162 v = __floats2bfloat162_rn(sm[seg * 8 + 2 * j][r],
                                                     sm[seg * 8 + 2 * j + 1][r]);
            pk[j] = *reinterpret_cast<uint32_t*>(&v);
        }
        size_t pix = ((size_t)b * HP_ + h + 1) * WP_ + (w0 + r + 1);
        reinterpret_cast<uint4*>(g_Egt + pix * C_)[seg] = make_uint4(pk[0], pk[1], pk[2], pk[3]);
    }
}

// ---------------------------------------------------------------------------
// Conv: per (b,h): D[128 oc, 128 pix] = sum_{9 taps} Wtap[128,64] @ Etap[128,64]^T
// mma.sync m16n8k16 bf16, cp.async double-buffered 32KB stages.
// 8 warps: warp tile 64(M) x 32(N). Epilogue: scale by 1/boxsum3x3(Cs).
// ---------------------------------------------------------------------------
#define STAGE_BYTES 32768
#define CONV_SMEM   (2 * STAGE_BYTES + 512)

__global__ __launch_bounds__(256, 1) void conv_mma_kernel(float* __restrict__ out) {
    extern __shared__ __align__(128) char smem[];
    const uint32_t sbase = smem_u32(smem);
    const int tid  = threadIdx.x;
    const int wid  = tid >> 5, lane = tid & 31;
    const int h = blockIdx.x, b = blockIdx.y;
    const int wm = wid & 1, wn = wid >> 1;    // 2 x 4 warp grid

    const char* EgB = reinterpret_cast<const char*>(g_Egt) + (size_t)b * HP_ * WP_ * C_ * 2;

    float acc[4][4][4];
#pragma unroll
    for (int i = 0; i < 4; i++)
#pragma unroll
        for (int j = 0; j < 4; j++)
#pragma unroll
            for (int k = 0; k < 4; k++) acc[i][j][k] = 0.f;

    // ---- async tap loader: A = Wr[t] (16KB), B = E row slab (16KB) ----
    auto issue_tap = [&](int t) {
        const int s = t & 1;
        const int kh = t / 3, kw = t % 3;
        const uint4* srcA = reinterpret_cast<const uint4*>(g_Wr + t * OC_ * C_);
        const uint4* srcB = reinterpret_cast<const uint4*>(
            EgB + (((size_t)(h + kh)) * WP_ + kw) * (C_ * 2));
        const uint32_t dA = sbase + s * STAGE_BYTES;
        const uint32_t dB = dA + 16384;
#pragma unroll
        for (int p = 0; p < 4; p++) {
            int c = p * 256 + tid;                  // 0..1023 16B chunks
            int off  = c * 16;
            int soff = off ^ ((off >> 3) & 0x70);   // SW128 swizzle
            CP_ASYNC16(dA + soff, srcA + c);
            CP_ASYNC16(dB + soff, srcB + c);
        }
        CP_COMMIT();
    };

    issue_tap(0);

#pragma unroll
    for (int t = 0; t < 9; t++) {
        if (t < 8) { issue_tap(t + 1); CP_WAIT(1); }
        else       { CP_WAIT(0); }
        __syncthreads();

        const uint32_t sA = sbase + (t & 1) * STAGE_BYTES;
        const uint32_t sB = sA + 16384;

#pragma unroll
        for (int ks = 0; ks < 4; ks++) {
            uint32_t a[4][4];
#pragma unroll
            for (int mi = 0; mi < 4; mi++) {
                int row = wm * 64 + mi * 16 + (lane & 15);
                int col = ks * 32 + ((lane >> 4) << 4);
                int off = row * 128 + col;
                int so  = off ^ ((off >> 3) & 0x70);
                LDSM_X4(a[mi][0], a[mi][1], a[mi][2], a[mi][3], sA + so);
            }
            uint32_t bf[2][4];   // bf[nb]: {b0,b1} for ni=2nb, {b0,b1} for ni=2nb+1
#pragma unroll
            for (int nb = 0; nb < 2; nb++) {
                int row = wn * 32 + nb * 16 + ((lane >> 4) << 3) + (lane & 7);
                int col = ks * 32 + (((lane >> 3) & 1) << 4);
                int off = row * 128 + col;
                int so  = off ^ ((off >> 3) & 0x70);
                LDSM_X4(bf[nb][0], bf[nb][1], bf[nb][2], bf[nb][3], sB + so);
            }
#pragma unroll
            for (int mi = 0; mi < 4; mi++)
#pragma unroll
                for (int ni = 0; ni < 4; ni++) {
                    uint32_t b0 = bf[ni >> 1][(ni & 1) * 2];
                    uint32_t b1 = bf[ni >> 1][(ni & 1) * 2 + 1];
                    mma16816(acc[mi][ni], a[mi], b0, b1);
                }
        }
        __syncthreads();
    }

    // ---- softmax denominator: rz[w] = 1 / boxsum3x3(Cs) ----
    float* rz = reinterpret_cast<float*>(smem + 2 * STAGE_BYTES);
    if (tid < 128) {
        const float* Cb = g_Cs + ((size_t)b * HP_ + h) * WP_ + tid;
        float s = 0.f;
#pragma unroll
        for (int i = 0; i < 3; i++)
#pragma unroll
            for (int j = 0; j < 3; j++) s += Cb[i * WP_ + j];
        rz[tid] = 1.0f / s;
    }
    __syncthreads();

    // ---- epilogue: scale + store ----
#pragma unroll
    for (int mi = 0; mi < 4; mi++)
#pragma unroll
        for (int ni = 0; ni < 4; ni++) {
            int oc = wm * 64 + mi * 16 + (lane >> 2);
            int w  = wn * 32 + ni * 8 + (lane & 3) * 2;
            float z0 = rz[w], z1 = rz[w + 1];
            float* p0 = out + (((size_t)b * OC_ + oc) * H_ + h) * W_ + w;
            float2 v0 = make_float2(acc[mi][ni][0] * z0, acc[mi][ni][1] * z1);
            float2 v1 = make_float2(acc[mi][ni][2] * z0, acc[mi][ni][3] * z1);
            *reinterpret_cast<float2*>(p0) = v0;
            *reinterpret_cast<float2*>(p0 + (size_t)8 * H_ * W_) = v1;
        }
}

// ---------------------------------------------------------------------------
extern "C" void kernel_launch(void* const* d_in, const int* in_sizes, int n_in,
                              void* d_out, int out_size) {
    const float* x   = (const float*)d_in[0];   // [8,64,128,128]
    const float* mem = (const float*)d_in[1];   // [576,128]
    float* out = (float*)d_out;                 // [8,128,128,128]

    cudaFuncSetAttribute(conv_mma_kernel,
                         cudaFuncAttributeMaxDynamicSharedMemorySize, CONV_SMEM);

    prep_w_kernel<<<(9 * OC_ * C_ + 255) / 256, 256>>>(mem);
    border_kernel<<<(B_ * 516 + 127) / 128, 128>>>();
    exp_kernel<<<dim3(2, H_, B_), 256>>>(x);

    conv_mma_kernel<<<dim3(H_, B_), 256, CONV_SMEM>>>(out);
}

// round 4
// speedup vs baseline: 7.3785x; 1.0512x over previous
#include <cuda_runtime.h>
#include <cuda_bf16.h>
#include <cstdint>

#define B_  8
#define C_  64
#define H_  128
#define W_  128
#define OC_ 128
#define HP_ 130
#define WP_ 130

#define ROWB 16640               // one padded row slab: 130 px * 64 ch * 2 B
#define SW_STAGE 16384
#define SE_OFF   (3 * SW_STAGE)              // 49152
#define RZ_OFF   (SE_OFF + 3 * ROWB)         // 99072
#define CONV_SMEM (RZ_OFF + 512)             // 99584

// E transposed: [b][hp][wp][c] bf16, border ring = 1.0 (= exp(0))
__device__ __nv_bfloat16 g_Egt[(size_t)B_ * HP_ * WP_ * C_];  // ~17.3 MB
__device__ float         g_Cs[(size_t)B_ * HP_ * WP_];        // channel sums, ring = 64
__device__ __nv_bfloat16 g_Wr[9 * OC_ * C_];                  // [tap][oc][c]

// ---------------------------------------------------------------------------
__device__ __forceinline__ uint32_t smem_u32(const void* p) {
    uint32_t a;
    asm("{ .reg .u64 t; cvta.to.shared.u64 t, %1; cvt.u32.u64 %0, t; }" : "=r"(a) : "l"(p));
    return a;
}
#define CP_ASYNC16(sa, ga) \
    asm volatile("cp.async.cg.shared.global [%0], [%1], 16;" :: "r"(sa), "l"(ga) : "memory")
#define CP_COMMIT() asm volatile("cp.async.commit_group;" ::: "memory")
#define CP_WAIT(n)  asm volatile("cp.async.wait_group %0;" :: "n"(n) : "memory")
#define LDSM_X4(r0, r1, r2, r3, addr) \
    asm volatile("ldmatrix.sync.aligned.m8n8.x4.shared.b16 {%0,%1,%2,%3}, [%4];" \
        : "=r"(r0), "=r"(r1), "=r"(r2), "=r"(r3) : "r"(addr))

__device__ __forceinline__ void mma16816(float* c, const uint32_t* a,
                                         uint32_t b0, uint32_t b1) {
    asm volatile(
        "mma.sync.aligned.m16n8k16.row.col.f32.bf16.bf16.f32 "
        "{%0,%1,%2,%3}, {%4,%5,%6,%7}, {%8,%9}, {%0,%1,%2,%3};"
        : "+f"(c[0]), "+f"(c[1]), "+f"(c[2]), "+f"(c[3])
        : "r"(a[0]), "r"(a[1]), "r"(a[2]), "r"(a[3]), "r"(b0), "r"(b1));
}

// ---------------------------------------------------------------------------
// Merged prep: Wr[tap][oc][c] bf16  +  border ring (Egt=1, Cs=64)
// ---------------------------------------------------------------------------
__global__ void prep_kernel(const float* __restrict__ mem) {
    int idx = blockIdx.x * 256 + threadIdx.x;
    if (idx < 9 * OC_ * C_) {
        int c   = idx & 63;
        int oc  = (idx >> 6) & 127;
        int tap = idx >> 13;
        g_Wr[idx] = __float2bfloat16(mem[(c * 9 + tap) * OC_ + oc]);
        return;
    }
    idx -= 9 * OC_ * C_;
    if (idx >= B_ * 516) return;
    int b = idx / 516, p = idx % 516;
    int hp, wp;
    if (p < 260) { hp = (p < 130) ? 0 : (HP_ - 1); wp = p % 130; }
    else { int q = p - 260; hp = 1 + (q & 127); wp = (q < 128) ? 0 : (WP_ - 1); }
    size_t pix = ((size_t)b * HP_ + hp) * WP_ + wp;
    uint4 ones = make_uint4(0x3F803F80u, 0x3F803F80u, 0x3F803F80u, 0x3F803F80u);
    uint4* dst = reinterpret_cast<uint4*>(g_Egt + pix * C_);
#pragma unroll
    for (int i = 0; i < 8; i++) dst[i] = ones;
    g_Cs[pix] = 64.0f;
}

// ---------------------------------------------------------------------------
// E = exp(x), transpose to channel-contiguous bf16, channel sums
// ---------------------------------------------------------------------------
__global__ __launch_bounds__(256) void exp_kernel(const float* __restrict__ x) {
    __shared__ float sm[C_][65];
    const int b = blockIdx.z, h = blockIdx.y, w0 = blockIdx.x * 64;
    const int tid = threadIdx.x;
    const int px = tid & 63, cq = tid >> 6;

    const float* xb = x + (((size_t)b * C_) * H_ + h) * W_ + w0 + px;
#pragma unroll
    for (int it = 0; it < 16; it++) {
        int c = it * 4 + cq;
        sm[c][px] = __expf(xb[(size_t)c * H_ * W_]);
    }
    __syncthreads();

    if (tid < 64) {
        float s = 0.f;
#pragma unroll
        for (int c = 0; c < C_; c++) s += sm[c][tid];
        g_Cs[((size_t)b * HP_ + h + 1) * WP_ + (w0 + tid + 1)] = s;
    }

    const int seg = tid & 7, r0 = tid >> 3;
#pragma unroll
    for (int pass = 0; pass < 2; pass++) {
        int r = pass * 32 + r0;
        uint32_t pk[4];
#pragma unroll
        for (int j = 0; j < 4; j++) {
            __nv_bfloat162 v = __floats2bfloat162_rn(sm[seg * 8 + 2 * j][r],
                                                     sm[seg * 8 + 2 * j + 1][r]);
            pk[j] = *reinterpret_cast<uint32_t*>(&v);
        }
        size_t pix = ((size_t)b * HP_ + h + 1) * WP_ + (w0 + r + 1);
        reinterpret_cast<uint4*>(g_Egt + pix * C_)[seg] = make_uint4(pk[0], pk[1], pk[2], pk[3]);
    }
}

// ---------------------------------------------------------------------------
// Conv: per (b,h): D[128 oc, 128 pix] = sum_{9 taps} Wtap[128,64] @ Etap[128,64]^T
// E rows h..h+2 resident in smem (kw = +128B row offset); W 3-stage cp.async.
// 8 warps, warp tile 64x32, one __syncthreads per tap. 2 CTAs/SM.
// ---------------------------------------------------------------------------
__global__ void __launch_bounds__(256, 2) conv_mma_kernel(float* __restrict__ out) {
    extern __shared__ __align__(128) char smem[];
    const uint32_t sbase = smem_u32(smem);
    const int tid  = threadIdx.x;
    const int wid  = tid >> 5, lane = tid & 31;
    const int h = blockIdx.x, b = blockIdx.y;
    const int wm = wid & 1, wn = wid >> 1;    // 2 x 4 warp grid

    const char* EgB = reinterpret_cast<const char*>(g_Egt) + (size_t)b * HP_ * WP_ * C_ * 2;

    auto issueW = [&](int t, int s) {
        const uint4* srcA = reinterpret_cast<const uint4*>(g_Wr + t * OC_ * C_);
        const uint32_t dA = sbase + s * SW_STAGE;
#pragma unroll
        for (int p = 0; p < 4; p++) {
            int c = p * 256 + tid;
            int off  = c * 16;
            int soff = off ^ ((off >> 3) & 0x70);
            CP_ASYNC16(dA + soff, srcA + c);
        }
    };

    // ---- prologue: E rows h..h+2 (one contiguous 49920B region) + W0; then W1
    {
        const char* srcE = EgB + (size_t)h * ROWB;
        for (int i = tid; i < 3120; i += 256) {
            int slab = i / 1040;
            int r    = i - slab * 1040;
            int off  = r * 16;
            int soff = off ^ ((off >> 3) & 0x70);
            CP_ASYNC16(sbase + SE_OFF + slab * ROWB + soff, srcE + (size_t)i * 16);
        }
    }
    issueW(0, 0); CP_COMMIT();   // g0 = E + W0
    issueW(1, 1); CP_COMMIT();   // g1 = W1

    float acc[4][4][4];
#pragma unroll
    for (int i = 0; i < 4; i++)
#pragma unroll
        for (int j = 0; j < 4; j++)
#pragma unroll
            for (int k = 0; k < 4; k++) acc[i][j][k] = 0.f;

#pragma unroll 1
    for (int t = 0; t < 9; t++) {
        if (t < 8) CP_WAIT(1); else CP_WAIT(0);
        __syncthreads();
        if (t < 7) { issueW(t + 2, (t + 2) % 3); CP_COMMIT(); }

        const int kh = t / 3, kw = t - 3 * kh;
        const uint32_t sA = sbase + (t % 3) * SW_STAGE;
        const uint32_t sE = sbase + SE_OFF + kh * ROWB;

#pragma unroll
        for (int ks = 0; ks < 4; ks++) {
            uint32_t a[4][4];
#pragma unroll
            for (int mi = 0; mi < 4; mi++) {
                int row = wm * 64 + mi * 16 + (lane & 15);
                int col = ks * 32 + ((lane >> 4) << 4);
                int off = row * 128 + col;
                int so  = off ^ ((off >> 3) & 0x70);
                LDSM_X4(a[mi][0], a[mi][1], a[mi][2], a[mi][3], sA + so);
            }
            uint32_t bf[2][4];
#pragma unroll
            for (int nb = 0; nb < 2; nb++) {
                int row = kw + wn * 32 + nb * 16 + ((lane >> 4) << 3) + (lane & 7);
                int col = ks * 32 + (((lane >> 3) & 1) << 4);
                int off = row * 128 + col;
                int so  = off ^ ((off >> 3) & 0x70);
                LDSM_X4(bf[nb][0], bf[nb][1], bf[nb][2], bf[nb][3], sE + so);
            }
#pragma unroll
            for (int mi = 0; mi < 4; mi++)
#pragma unroll
                for (int ni = 0; ni < 4; ni++) {
                    uint32_t b0 = bf[ni >> 1][(ni & 1) * 2];
                    uint32_t b1 = bf[ni >> 1][(ni & 1) * 2 + 1];
                    mma16816(acc[mi][ni], a[mi], b0, b1);
                }
        }
    }

    // ---- softmax denominator: rz[w] = 1 / boxsum3x3(Cs) ----
    float* rz = reinterpret_cast<float*>(smem + RZ_OFF);
    if (tid < 128) {
        const float* Cb = g_Cs + ((size_t)b * HP_ + h) * WP_ + tid;
        float s = 0.f;
#pragma unroll
        for (int i = 0; i < 3; i++)
#pragma unroll
            for (int j = 0; j < 3; j++) s += Cb[i * WP_ + j];
        rz[tid] = 1.0f / s;
    }
    __syncthreads();

    // ---- epilogue: scale + store ----
#pragma unroll
    for (int mi = 0; mi < 4; mi++)
#pragma unroll
        for (int ni = 0; ni < 4; ni++) {
            int oc = wm * 64 + mi * 16 + (lane >> 2);
            int w  = wn * 32 + ni * 8 + (lane & 3) * 2;
            float z0 = rz[w], z1 = rz[w + 1];
            float* p0 = out + (((size_t)b * OC_ + oc) * H_ + h) * W_ + w;
            float2 v0 = make_float2(acc[mi][ni][0] * z0, acc[mi][ni][1] * z1);
            float2 v1 = make_float2(acc[mi][ni][2] * z0, acc[mi][ni][3] * z1);
            *reinterpret_cast<float2*>(p0) = v0;
            *reinterpret_cast<float2*>(p0 + (size_t)8 * H_ * W_) = v1;
        }
}

// ---------------------------------------------------------------------------
extern "C" void kernel_launch(void* const* d_in, const int* in_sizes, int n_in,
                              void* d_out, int out_size) {
    const float* x   = (const float*)d_in[0];   // [8,64,128,128]
    const float* mem = (const float*)d_in[1];   // [576,128]
    float* out = (float*)d_out;                 // [8,128,128,128]

    cudaFuncSetAttribute(conv_mma_kernel,
                         cudaFuncAttributeMaxDynamicSharedMemorySize, CONV_SMEM);

    int prep_total = 9 * OC_ * C_ + B_ * 516;
    prep_kernel<<<(prep_total + 255) / 256, 256>>>(mem);
    exp_kernel<<<dim3(2, H_, B_), 256>>>(x);

    conv_mma_kernel<<<dim3(H_, B_), 256, CONV_SMEM>>>(out);
}

// round 5
// speedup vs baseline: 7.5180x; 1.0189x over previous
#include <cuda_runtime.h>
#include <cuda_bf16.h>
#include <cstdint>

#define B_  8
#define C_  64
#define H_  128
#define W_  128
#define OC_ 128
#define HP_ 130
#define WP_ 130

#define ROWB 16640               // one padded row slab: 130 px * 64 ch * 2 B
#define SW_STAGE 16384
#define SE_OFF   (3 * SW_STAGE)              // 49152
#define RZ_OFF   (SE_OFF + 3 * ROWB)         // 99072
#define CONV_SMEM (RZ_OFF + 512)             // 99584

// E transposed: [b][hp][wp][c] bf16, border ring = 1.0 (= exp(0))
__device__ __nv_bfloat16 g_Egt[(size_t)B_ * HP_ * WP_ * C_];  // ~17.3 MB
__device__ float         g_Cs[(size_t)B_ * HP_ * WP_];        // channel sums, ring = 64
__device__ __nv_bfloat16 g_Wr[9 * OC_ * C_];                  // [tap][oc][c]

// ---------------------------------------------------------------------------
__device__ __forceinline__ uint32_t smem_u32(const void* p) {
    uint32_t a;
    asm("{ .reg .u64 t; cvta.to.shared.u64 t, %1; cvt.u32.u64 %0, t; }" : "=r"(a) : "l"(p));
    return a;
}
#define CP_ASYNC16(sa, ga) \
    asm volatile("cp.async.cg.shared.global [%0], [%1], 16;" :: "r"(sa), "l"(ga) : "memory")
#define CP_COMMIT() asm volatile("cp.async.commit_group;" ::: "memory")
#define CP_WAIT(n)  asm volatile("cp.async.wait_group %0;" :: "n"(n) : "memory")
#define LDSM_X4(r0, r1, r2, r3, addr) \
    asm volatile("ldmatrix.sync.aligned.m8n8.x4.shared.b16 {%0,%1,%2,%3}, [%4];" \
        : "=r"(r0), "=r"(r1), "=r"(r2), "=r"(r3) : "r"(addr))

__device__ __forceinline__ void mma16816(float* c, const uint32_t* a,
                                         uint32_t b0, uint32_t b1) {
    asm volatile(
        "mma.sync.aligned.m16n8k16.row.col.f32.bf16.bf16.f32 "
        "{%0,%1,%2,%3}, {%4,%5,%6,%7}, {%8,%9}, {%0,%1,%2,%3};"
        : "+f"(c[0]), "+f"(c[1]), "+f"(c[2]), "+f"(c[3])
        : "r"(a[0]), "r"(a[1]), "r"(a[2]), "r"(a[3]), "r"(b0), "r"(b1));
}

// ---------------------------------------------------------------------------
// Fused pre-kernel: blocks [0,2048): exp+transpose+chansum
//                   blocks [2048,..): weight rearrange + border ring
// ---------------------------------------------------------------------------
#define EXP_BLOCKS 2048
#define PREP_TOTAL (9 * OC_ * C_ + B_ * 516)          // 9216*... = 13344
#define PRE_GRID   (EXP_BLOCKS + (PREP_TOTAL + 255) / 256)

__global__ __launch_bounds__(256) void pre_kernel(const float* __restrict__ x,
                                                  const float* __restrict__ mem) {
    const int bid = blockIdx.x;
    const int tid = threadIdx.x;

    if (bid >= EXP_BLOCKS) {
        int idx = (bid - EXP_BLOCKS) * 256 + tid;
        if (idx < 9 * OC_ * C_) {
            int c   = idx & 63;
            int oc  = (idx >> 6) & 127;
            int tap = idx >> 13;
            g_Wr[idx] = __float2bfloat16(mem[(c * 9 + tap) * OC_ + oc]);
            return;
        }
        idx -= 9 * OC_ * C_;
        if (idx >= B_ * 516) return;
        int b = idx / 516, p = idx % 516;
        int hp, wp;
        if (p < 260) { hp = (p < 130) ? 0 : (HP_ - 1); wp = p % 130; }
        else { int q = p - 260; hp = 1 + (q & 127); wp = (q < 128) ? 0 : (WP_ - 1); }
        size_t pix = ((size_t)b * HP_ + hp) * WP_ + wp;
        uint4 ones = make_uint4(0x3F803F80u, 0x3F803F80u, 0x3F803F80u, 0x3F803F80u);
        uint4* dst = reinterpret_cast<uint4*>(g_Egt + pix * C_);
#pragma unroll
        for (int i = 0; i < 8; i++) dst[i] = ones;
        g_Cs[pix] = 64.0f;
        return;
    }

    // ---- exp part: one h row, 64 pixels x 64 channels ----
    __shared__ float sm[C_][65];
    const int w0 = (bid & 1) * 64;
    const int h  = (bid >> 1) & 127;
    const int b  = bid >> 8;
    const int px = tid & 63, cq = tid >> 6;

    const float* xb = x + (((size_t)b * C_) * H_ + h) * W_ + w0 + px;
#pragma unroll
    for (int it = 0; it < 16; it++) {
        int c = it * 4 + cq;
        sm[c][px] = __expf(xb[(size_t)c * H_ * W_]);
    }
    __syncthreads();

    if (tid < 64) {
        float s = 0.f;
#pragma unroll
        for (int c = 0; c < C_; c++) s += sm[c][tid];
        g_Cs[((size_t)b * HP_ + h + 1) * WP_ + (w0 + tid + 1)] = s;
    }

    const int seg = tid & 7, r0 = tid >> 3;
#pragma unroll
    for (int pass = 0; pass < 2; pass++) {
        int r = pass * 32 + r0;
        uint32_t pk[4];
#pragma unroll
        for (int j = 0; j < 4; j++) {
            __nv_bfloat162 v = __floats2bfloat162_rn(sm[seg * 8 + 2 * j][r],
                                                     sm[seg * 8 + 2 * j + 1][r]);
            pk[j] = *reinterpret_cast<uint32_t*>(&v);
        }
        size_t pix = ((size_t)b * HP_ + h + 1) * WP_ + (w0 + r + 1);
        reinterpret_cast<uint4*>(g_Egt + pix * C_)[seg] = make_uint4(pk[0], pk[1], pk[2], pk[3]);
    }
}

// ---------------------------------------------------------------------------
// Conv: per (b,h): D[128 oc, 128 pix] = sum_{9 taps} Wtap[128,64] @ Etap[128,64]^T
// ---------------------------------------------------------------------------
__global__ void __launch_bounds__(256, 2) conv_mma_kernel(float* __restrict__ out) {
    extern __shared__ __align__(128) char smem[];
    const uint32_t sbase = smem_u32(smem);
    const int tid  = threadIdx.x;
    const int wid  = tid >> 5, lane = tid & 31;
    const int h = blockIdx.x, b = blockIdx.y;
    const int wm = wid & 1, wn = wid >> 1;    // 2 x 4 warp grid

    const char* EgB = reinterpret_cast<const char*>(g_Egt) + (size_t)b * HP_ * WP_ * C_ * 2;

    auto issueW = [&](int t, int s) {
        const uint4* srcA = reinterpret_cast<const uint4*>(g_Wr + t * OC_ * C_);
        const uint32_t dA = sbase + s * SW_STAGE;
#pragma unroll
        for (int p = 0; p < 4; p++) {
            int c = p * 256 + tid;
            int off  = c * 16;
            int soff = off ^ ((off >> 3) & 0x70);
            CP_ASYNC16(dA + soff, srcA + c);
        }
    };

    // ---- prologue: E rows h..h+2 (contiguous 49920B) + W0; then W1 ----
    {
        const char* srcE = EgB + (size_t)h * ROWB;
        for (int i = tid; i < 3120; i += 256) {
            int slab = i / 1040;
            int r    = i - slab * 1040;
            int off  = r * 16;
            int soff = off ^ ((off >> 3) & 0x70);
            CP_ASYNC16(sbase + SE_OFF + slab * ROWB + soff, srcE + (size_t)i * 16);
        }
    }
    issueW(0, 0); CP_COMMIT();   // g0 = E + W0
    issueW(1, 1); CP_COMMIT();   // g1 = W1

    // ---- softmax denominator early (overlaps cp.async) ----
    float* rz = reinterpret_cast<float*>(smem + RZ_OFF);
    if (tid < 128) {
        const float* Cb = g_Cs + ((size_t)b * HP_ + h) * WP_ + tid;
        float s = 0.f;
#pragma unroll
        for (int i = 0; i < 3; i++)
#pragma unroll
            for (int j = 0; j < 3; j++) s += Cb[i * WP_ + j];
        rz[tid] = 1.0f / s;
    }

    float acc[4][4][4];
#pragma unroll
    for (int i = 0; i < 4; i++)
#pragma unroll
        for (int j = 0; j < 4; j++)
#pragma unroll
            for (int k = 0; k < 4; k++) acc[i][j][k] = 0.f;

    // Precomputed per-warp addressing (row*128 | swizzle-xor terms)
    int aRow[4], aSw[4];
#pragma unroll
    for (int mi = 0; mi < 4; mi++) {
        int row = wm * 64 + mi * 16 + (lane & 15);
        aRow[mi] = row * 128;
        aSw[mi]  = (row & 7) * 16;
    }
    const int aCol = (lane >> 4) << 4;
    int bRowBase[2];
#pragma unroll
    for (int nb = 0; nb < 2; nb++)
        bRowBase[nb] = wn * 32 + nb * 16 + ((lane >> 4) << 3) + (lane & 7);
    const int bCol = ((lane >> 3) & 1) << 4;

#pragma unroll 1
    for (int t = 0; t < 9; t++) {
        if (t < 8) CP_WAIT(1); else CP_WAIT(0);
        __syncthreads();
        if (t < 7) { issueW(t + 2, (t + 2) % 3); CP_COMMIT(); }

        const int kh = t / 3, kw = t - 3 * kh;
        const uint32_t sA = sbase + (t % 3) * SW_STAGE;
        const uint32_t sE = sbase + SE_OFF + kh * ROWB;

#pragma unroll
        for (int ks = 0; ks < 4; ks++) {
            uint32_t a[4][4];
#pragma unroll
            for (int mi = 0; mi < 4; mi++) {
                uint32_t addr = sA + aRow[mi] + ((ks * 32 + aCol) ^ aSw[mi]);
                LDSM_X4(a[mi][0], a[mi][1], a[mi][2], a[mi][3], addr);
            }
            uint32_t bf[2][4];
#pragma unroll
            for (int nb = 0; nb < 2; nb++) {
                int row = bRowBase[nb] + kw;
                uint32_t addr = sE + row * 128 + ((ks * 32 + bCol) ^ ((row & 7) * 16));
                LDSM_X4(bf[nb][0], bf[nb][1], bf[nb][2], bf[nb][3], addr);
            }
#pragma unroll
            for (int mi = 0; mi < 4; mi++)
#pragma unroll
                for (int ni = 0; ni < 4; ni++) {
                    uint32_t b0 = bf[ni >> 1][(ni & 1) * 2];
                    uint32_t b1 = bf[ni >> 1][(ni & 1) * 2 + 1];
                    mma16816(acc[mi][ni], a[mi], b0, b1);
                }
        }
    }
    __syncthreads();

    // ---- epilogue: scale + store ----
#pragma unroll
    for (int mi = 0; mi < 4; mi++)
#pragma unroll
        for (int ni = 0; ni < 4; ni++) {
            int oc = wm * 64 + mi * 16 + (lane >> 2);
            int w  = wn * 32 + ni * 8 + (lane & 3) * 2;
            float z0 = rz[w], z1 = rz[w + 1];
            float* p0 = out + (((size_t)b * OC_ + oc) * H_ + h) * W_ + w;
            float2 v0 = make_float2(acc[mi][ni][0] * z0, acc[mi][ni][1] * z1);
            float2 v1 = make_float2(acc[mi][ni][2] * z0, acc[mi][ni][3] * z1);
            *reinterpret_cast<float2*>(p0) = v0;
            *reinterpret_cast<float2*>(p0 + (size_t)8 * H_ * W_) = v1;
        }
}

// ---------------------------------------------------------------------------
extern "C" void kernel_launch(void* const* d_in, const int* in_sizes, int n_in,
                              void* d_out, int out_size) {
    const float* x   = (const float*)d_in[0];   // [8,64,128,128]
    const float* mem = (const float*)d_in[1];   // [576,128]
    float* out = (float*)d_out;                 // [8,128,128,128]

    cudaFuncSetAttribute(conv_mma_kernel,
                         cudaFuncAttributeMaxDynamicSharedMemorySize, CONV_SMEM);

    pre_kernel<<<PRE_GRID, 256>>>(x, mem);
    conv_mma_kernel<<<dim3(H_, B_), 256, CONV_SMEM>>>(out);
}